// round 2
// baseline (speedup 1.0000x reference)
#include <cuda_runtime.h>
#include <cstdint>

// D (hidden size) is fixed at 128 for this problem family.
#define HID 128

// Per-relation transformed table: T[r] = rel_features[r] @ W.T + b
// R = 2000 in this problem; reserve 2048 rows (1 MB static device scratch).
__device__ float g_T[2048 * HID];

// ---------------------------------------------------------------------------
// Kernel 1: T[r][o] = b[o] + sum_i rel_features[r][i] * W[o][i]
// One block per relation, 128 threads (one per output column).
// ---------------------------------------------------------------------------
__global__ void __launch_bounds__(HID) transform_kernel(
    const float* __restrict__ rel_features,
    const float* __restrict__ W,
    const float* __restrict__ b)
{
    __shared__ float x[HID];
    const int r = blockIdx.x;
    const int o = threadIdx.x;
    x[o] = rel_features[r * HID + o];
    __syncthreads();

    const float4* __restrict__ Wrow = (const float4*)(W + o * HID);
    float acc = b[o];
#pragma unroll
    for (int i = 0; i < HID / 4; i++) {
        float4 w = Wrow[i];
        acc += w.x * x[4 * i + 0];
        acc += w.y * x[4 * i + 1];
        acc += w.z * x[4 * i + 2];
        acc += w.w * x[4 * i + 3];
    }
    g_T[r * HID + o] = acc;
}

// ---------------------------------------------------------------------------
// Kernel 2: scatter-add. One warp per fact; lane L owns columns [4L, 4L+4).
// out[tail]+=v*T[rel], out[head]+=v*T[rel] via vectorized L2 reductions.
// Output region is 8 MB -> fully L2 resident, atomics never touch DRAM.
// ---------------------------------------------------------------------------
__device__ __forceinline__ void red_add_v4(float* addr, float4 v) {
    asm volatile("red.global.add.v4.f32 [%0], {%1, %2, %3, %4};"
                 :: "l"(addr), "f"(v.x), "f"(v.y), "f"(v.z), "f"(v.w)
                 : "memory");
}

__global__ void __launch_bounds__(256) scatter_kernel(
    const int* __restrict__ heads,
    const int* __restrict__ tails,
    const int* __restrict__ rels,
    const float* __restrict__ val,
    float* __restrict__ out,
    int E)
{
    const int lane   = threadIdx.x & 31;
    const int warp   = (blockIdx.x * blockDim.x + threadIdx.x) >> 5;
    const int nwarps = (gridDim.x * blockDim.x) >> 5;

    for (int f = warp; f < E; f += nwarps) {
        // All lanes read the same fact scalars (L1 broadcast, line-coalesced
        // across the 8 warps of a block).
        const int   r = __ldg(rels  + f);
        const int   t = __ldg(tails + f);
        const int   h = __ldg(heads + f);
        const float v = __ldg(val   + f);

        float4 tv = *(const float4*)(g_T + r * HID + lane * 4);
        tv.x *= v; tv.y *= v; tv.z *= v; tv.w *= v;

        red_add_v4(out + (size_t)t * HID + lane * 4, tv);
        red_add_v4(out + (size_t)h * HID + lane * 4, tv);
    }
}

// ---------------------------------------------------------------------------
// Kernel 3: in-place ReLU over the accumulated output.
// ---------------------------------------------------------------------------
__global__ void __launch_bounds__(256) relu_kernel(float4* __restrict__ out, int n4)
{
    int i = blockIdx.x * blockDim.x + threadIdx.x;
    if (i < n4) {
        float4 v = out[i];
        v.x = fmaxf(v.x, 0.0f);
        v.y = fmaxf(v.y, 0.0f);
        v.z = fmaxf(v.z, 0.0f);
        v.w = fmaxf(v.w, 0.0f);
        out[i] = v;
    }
}

// ---------------------------------------------------------------------------
// Inputs (metadata order):
//   0: local_entity  int32 [B,M]      (unused by the reference math)
//   1: batch_heads   int32 [E]
//   2: batch_tails   int32 [E]
//   3: batch_rels    int32 [E]
//   4: val_one       f32   [E]
//   5: rel_features  f32   [R,128]
//   6: W             f32   [128,128]
//   7: b             f32   [128]
// Output: f32 [B,M,128] == [num_ent,128]
// ---------------------------------------------------------------------------
extern "C" void kernel_launch(void* const* d_in, const int* in_sizes, int n_in,
                              void* d_out, int out_size)
{
    const int*   heads        = (const int*)  d_in[1];
    const int*   tails        = (const int*)  d_in[2];
    const int*   rels         = (const int*)  d_in[3];
    const float* val          = (const float*)d_in[4];
    const float* rel_features = (const float*)d_in[5];
    const float* W            = (const float*)d_in[6];
    const float* b            = (const float*)d_in[7];
    float*       out          = (float*)d_out;

    const int E = in_sizes[1];
    const int R = in_sizes[5] / HID;

    // Output accumulator starts at zero (d_out is poisoned by the harness).
    cudaMemsetAsync(out, 0, (size_t)out_size * sizeof(float));

    // 1) Per-relation linear transform into L2-resident table.
    transform_kernel<<<R, HID>>>(rel_features, W, b);

    // 2) Scatter-add all facts (head + tail) with vectorized L2 atomics.
    //    1024 blocks x 256 threads = 8192 warps (~55/SM), grid-stride over E.
    scatter_kernel<<<1024, 256>>>(heads, tails, rels, val, out, E);

    // 3) ReLU epilogue.
    const int n4 = out_size / 4;
    relu_kernel<<<(n4 + 255) / 256, 256>>>((float4*)out, n4);
}

// round 3
// speedup vs baseline: 1.5421x; 1.5421x over previous
#include <cuda_runtime.h>
#include <cstdint>

#define HID     128
#define RC      256                 // relations per chunk (chunk = rel >> 8)
#define NC_MAX  8
#define MAX_R   2048
#define MAX_ENT 16384
#define MAX_KEYS (MAX_ENT * NC_MAX) // 131072
#define MAX_PAIRS 4400000           // 2*E capacity

// ---- static device scratch (no allocation allowed) ----
__device__ float              g_T[MAX_R * HID];       // transformed relation table (1 MB)
__device__ int                g_cnt[MAX_KEYS];        // per-(entity,chunk) counts
__device__ int                g_offs[MAX_KEYS];       // exclusive offsets
__device__ int                g_cursor[MAX_KEYS];     // fill cursors
__device__ int                g_blockSums[512];       // scan partials
__device__ unsigned long long g_payload[MAX_PAIRS];   // packed (val<<32 | rel)

// ---------------------------------------------------------------------------
// Zero the counters.
// ---------------------------------------------------------------------------
__global__ void zero_kernel(int n) {
    int i = blockIdx.x * blockDim.x + threadIdx.x;
    if (i < n) g_cnt[i] = 0;
}

// ---------------------------------------------------------------------------
// Transform: T[r] = rel_features[r] @ W.T + b.  W lives in smem (padded rows,
// conflict-free); each block handles ~R/grid relations.
// smem: Ws[128][129] + xs[128]
// ---------------------------------------------------------------------------
__global__ void __launch_bounds__(HID) transform_kernel(
    const float* __restrict__ rel_features,
    const float* __restrict__ W,
    const float* __restrict__ b,
    int R)
{
    extern __shared__ float sm[];
    float* Ws = sm;                  // 128*129 floats
    float* xs = sm + HID * 129;      // 128 floats

    const int t = threadIdx.x;
    // cooperative load of W with padding
    for (int idx = t; idx < HID * HID; idx += HID) {
        int o = idx >> 7, i = idx & 127;
        Ws[o * 129 + i] = W[idx];
    }
    const float bt = b[t];
    const float* wrow = Ws + t * 129;

    for (int r = blockIdx.x; r < R; r += gridDim.x) {
        __syncthreads();
        xs[t] = rel_features[r * HID + t];
        __syncthreads();
        float a0 = 0.f, a1 = 0.f, a2 = 0.f, a3 = 0.f;
#pragma unroll
        for (int i = 0; i < HID; i += 4) {
            a0 = fmaf(wrow[i + 0], xs[i + 0], a0);
            a1 = fmaf(wrow[i + 1], xs[i + 1], a1);
            a2 = fmaf(wrow[i + 2], xs[i + 2], a2);
            a3 = fmaf(wrow[i + 3], xs[i + 3], a3);
        }
        g_T[r * HID + t] = bt + ((a0 + a1) + (a2 + a3));
    }
}

// ---------------------------------------------------------------------------
// CSR build phase 1: count entries per (entity, chunk) bucket.
// ---------------------------------------------------------------------------
__global__ void count_kernel(const int* __restrict__ heads,
                             const int* __restrict__ tails,
                             const int* __restrict__ rels,
                             int E, int NC)
{
    int stride = gridDim.x * blockDim.x;
    for (int f = blockIdx.x * blockDim.x + threadIdx.x; f < E; f += stride) {
        int c = rels[f] >> 8;
        atomicAdd(&g_cnt[tails[f] * NC + c], 1);
        atomicAdd(&g_cnt[heads[f] * NC + c], 1);
    }
}

// ---------------------------------------------------------------------------
// Scan: block-local exclusive scan + block sums, then serial scan of block
// sums, then add-back (and init cursors).
// ---------------------------------------------------------------------------
__global__ void scan1_kernel(int N) {
    __shared__ int s[1024];
    int i = blockIdx.x * 1024 + threadIdx.x;
    int x = (i < N) ? g_cnt[i] : 0;
    s[threadIdx.x] = x;
    __syncthreads();
    for (int d = 1; d < 1024; d <<= 1) {
        int y = (threadIdx.x >= d) ? s[threadIdx.x - d] : 0;
        __syncthreads();
        s[threadIdx.x] += y;
        __syncthreads();
    }
    if (i < N) g_offs[i] = s[threadIdx.x] - x;   // exclusive within block
    if (threadIdx.x == 1023) g_blockSums[blockIdx.x] = s[1023];
}

__global__ void scan2_kernel(int nb) {
    if (blockIdx.x == 0 && threadIdx.x == 0) {
        int run = 0;
        for (int bIdx = 0; bIdx < nb; bIdx++) {
            int v = g_blockSums[bIdx];
            g_blockSums[bIdx] = run;
            run += v;
        }
    }
}

__global__ void scan3_kernel(int N) {
    int i = blockIdx.x * blockDim.x + threadIdx.x;
    if (i < N) {
        int o = g_offs[i] + g_blockSums[i >> 10];
        g_offs[i]   = o;
        g_cursor[i] = o;
    }
}

// ---------------------------------------------------------------------------
// CSR build phase 2: fill packed (val, rel) payloads.
// ---------------------------------------------------------------------------
__global__ void fill_kernel(const int* __restrict__ heads,
                            const int* __restrict__ tails,
                            const int* __restrict__ rels,
                            const float* __restrict__ val,
                            int E, int NC)
{
    int stride = gridDim.x * blockDim.x;
    for (int f = blockIdx.x * blockDim.x + threadIdx.x; f < E; f += stride) {
        int r   = rels[f];
        int c   = r >> 8;
        unsigned long long p =
            ((unsigned long long)__float_as_uint(val[f]) << 32) | (unsigned)r;
        int pt = atomicAdd(&g_cursor[tails[f] * NC + c], 1);
        g_payload[pt] = p;
        int ph = atomicAdd(&g_cursor[heads[f] * NC + c], 1);
        g_payload[ph] = p;
    }
}

// ---------------------------------------------------------------------------
// Gather: chunk-tiled over relations. T chunk (256 rows x 512B = 128KB) in
// smem; each warp owns up to 8 entities (strided), register accumulators,
// fused ReLU + single store per output row.
// ---------------------------------------------------------------------------
__global__ void __launch_bounds__(512) gather_kernel(
    float* __restrict__ out, int num_ent, int R, int NC)
{
    extern __shared__ float4 Ts[];   // RC * 32 float4s
    const int tid  = threadIdx.x;
    const int lane = tid & 31;
    const int gw   = blockIdx.x * (blockDim.x >> 5) + (tid >> 5);
    const int totW = gridDim.x * (blockDim.x >> 5);

    float4 acc[8];
#pragma unroll
    for (int k = 0; k < 8; k++) acc[k] = make_float4(0.f, 0.f, 0.f, 0.f);

    const float4* __restrict__ Tg = (const float4*)g_T;

    for (int c = 0; c < NC; c++) {
        int rows = min(RC, R - c * RC);
        __syncthreads();
        for (int idx = tid; idx < rows * 32; idx += blockDim.x)
            Ts[idx] = Tg[c * RC * 32 + idx];
        __syncthreads();

#pragma unroll
        for (int k = 0; k < 8; k++) {
            int e = gw + k * totW;
            if (e >= num_ent) break;
            int key = e * NC + c;
            int s0  = g_offs[key];
            int n   = g_cnt[key];
            float4 a = acc[k];
            for (int base = 0; base < n; base += 32) {
                unsigned long long pe = 0;
                if (base + lane < n) pe = g_payload[s0 + base + lane];
                int m = min(32, n - base);
                for (int j = 0; j < m; j++) {
                    unsigned long long p = __shfl_sync(0xffffffffu, pe, j);
                    int   rl = (int)(p & 0xffffffffull) - c * RC;
                    float v  = __uint_as_float((unsigned)(p >> 32));
                    float4 t = Ts[rl * 32 + lane];
                    a.x = fmaf(v, t.x, a.x);
                    a.y = fmaf(v, t.y, a.y);
                    a.z = fmaf(v, t.z, a.z);
                    a.w = fmaf(v, t.w, a.w);
                }
            }
            acc[k] = a;
        }
    }

#pragma unroll
    for (int k = 0; k < 8; k++) {
        int e = gw + k * totW;
        if (e >= num_ent) break;
        float4 a = acc[k];
        a.x = fmaxf(a.x, 0.f); a.y = fmaxf(a.y, 0.f);
        a.z = fmaxf(a.z, 0.f); a.w = fmaxf(a.w, 0.f);
        ((float4*)out)[(size_t)e * 32 + lane] = a;
    }
}

// ---------------------------------------------------------------------------
// Inputs (metadata order):
//   0: local_entity  int32 [B,M]   (unused)
//   1: batch_heads   int32 [E]
//   2: batch_tails   int32 [E]
//   3: batch_rels    int32 [E]
//   4: val_one       f32   [E]
//   5: rel_features  f32   [R,128]
//   6: W             f32   [128,128]
//   7: b             f32   [128]
// Output: f32 [num_ent, 128]
// ---------------------------------------------------------------------------
extern "C" void kernel_launch(void* const* d_in, const int* in_sizes, int n_in,
                              void* d_out, int out_size)
{
    const int*   heads = (const int*)  d_in[1];
    const int*   tails = (const int*)  d_in[2];
    const int*   rels  = (const int*)  d_in[3];
    const float* val   = (const float*)d_in[4];
    const float* rel_f = (const float*)d_in[5];
    const float* W     = (const float*)d_in[6];
    const float* b     = (const float*)d_in[7];
    float*       out   = (float*)d_out;

    const int E       = in_sizes[1];
    const int R       = in_sizes[5] / HID;
    const int num_ent = out_size / HID;
    const int NC      = (R + RC - 1) / RC;
    const int Nkeys   = num_ent * NC;
    const int nb      = (Nkeys + 1023) / 1024;

    const int TSM = (HID * 129 + HID) * sizeof(float);     // 66560 B
    const int GSM = RC * HID * sizeof(float);              // 131072 B
    cudaFuncSetAttribute(transform_kernel,
                         cudaFuncAttributeMaxDynamicSharedMemorySize, TSM);
    cudaFuncSetAttribute(gather_kernel,
                         cudaFuncAttributeMaxDynamicSharedMemorySize, GSM);

    zero_kernel<<<(Nkeys + 255) / 256, 256>>>(Nkeys);
    transform_kernel<<<148, HID, TSM>>>(rel_f, W, b, R);
    count_kernel<<<2048, 256>>>(heads, tails, rels, E, NC);
    scan1_kernel<<<nb, 1024>>>(Nkeys);
    scan2_kernel<<<1, 32>>>(nb);
    scan3_kernel<<<(Nkeys + 255) / 256, 256>>>(Nkeys);
    fill_kernel<<<2048, 256>>>(heads, tails, rels, val, E, NC);
    gather_kernel<<<148, 512, GSM>>>(out, num_ent, R, NC);
}

// round 5
// speedup vs baseline: 2.3229x; 1.5063x over previous
#include <cuda_runtime.h>
#include <cuda_fp16.h>
#include <cstdint>

#define HID    128
#define KPAD   2048            // padded K (relations)
#define MAXE   16384           // padded entity rows
#define KB     64              // K per pipeline chunk (64 halves = 128 B rows)
#define NCH    (KPAD / KB)     // 32 chunks
#define STG_BYTES 32768        // A(16KB)+B(16KB) per stage
#define SMEM_TOT  (2 * STG_BYTES)

// ---- static device scratch ----
__device__ __half g_S [MAXE * KPAD];   // dense incidence-value matrix (64 MB)
__device__ __half g_Bt[HID  * KPAD];   // Bt[n][k] = transformed table, transposed (512 KB)

// ===========================================================================
// helpers
// ===========================================================================
__device__ __forceinline__ uint32_t smem_u32(const void* p) {
    uint32_t a;
    asm("{ .reg .u64 t; cvta.to.shared.u64 t, %1; cvt.u32.u64 %0, t; }"
        : "=r"(a) : "l"(p));
    return a;
}
__device__ __forceinline__ void cp_async16(uint32_t dst, const void* src) {
    asm volatile("cp.async.cg.shared.global [%0], [%1], 16;"
                 :: "r"(dst), "l"(src) : "memory");
}
__device__ __forceinline__ void ldsm_x4(uint32_t& r0, uint32_t& r1,
                                        uint32_t& r2, uint32_t& r3, uint32_t a) {
    asm volatile("ldmatrix.sync.aligned.m8n8.x4.shared.b16 {%0,%1,%2,%3}, [%4];"
                 : "=r"(r0), "=r"(r1), "=r"(r2), "=r"(r3) : "r"(a));
}
__device__ __forceinline__ void mma16816(float* c, const uint32_t* a,
                                         uint32_t b0, uint32_t b1) {
    asm volatile(
        "mma.sync.aligned.m16n8k16.row.col.f32.f16.f16.f32 "
        "{%0,%1,%2,%3}, {%4,%5,%6,%7}, {%8,%9}, {%0,%1,%2,%3};"
        : "+f"(c[0]), "+f"(c[1]), "+f"(c[2]), "+f"(c[3])
        : "r"(a[0]), "r"(a[1]), "r"(a[2]), "r"(a[3]), "r"(b0), "r"(b1));
}
// XOR swizzle of a 16B chunk index within a 128B row
#define SWZ_OFF(row, chunk) (((row) * 128) + ((((chunk) ^ ((row) & 7))) << 4))

// ===========================================================================
// Transform: Bt[o][r] = b[o] + sum_i rel_features[r][i] * W[o][i]
// ===========================================================================
__global__ void __launch_bounds__(HID) transform_kernel(
    const float* __restrict__ rel_features,
    const float* __restrict__ W,
    const float* __restrict__ b,
    int R)
{
    extern __shared__ float sm[];
    float* Ws = sm;               // 128*129 padded
    float* xs = sm + HID * 129;

    const int t = threadIdx.x;
    for (int idx = t; idx < HID * HID; idx += HID) {
        int o = idx >> 7, i = idx & 127;
        Ws[o * 129 + i] = W[idx];
    }
    const float bt = b[t];
    const float* wrow = Ws + t * 129;

    for (int r = blockIdx.x; r < R; r += gridDim.x) {
        __syncthreads();
        xs[t] = rel_features[r * HID + t];
        __syncthreads();
        float a0 = 0.f, a1 = 0.f, a2 = 0.f, a3 = 0.f;
#pragma unroll
        for (int i = 0; i < HID; i += 4) {
            a0 = fmaf(wrow[i + 0], xs[i + 0], a0);
            a1 = fmaf(wrow[i + 1], xs[i + 1], a1);
            a2 = fmaf(wrow[i + 2], xs[i + 2], a2);
            a3 = fmaf(wrow[i + 3], xs[i + 3], a3);
        }
        g_Bt[t * KPAD + r] = __float2half(bt + ((a0 + a1) + (a2 + a3)));
    }
}

// ===========================================================================
// Fill dense S with fp16 L2 atomics: S[tail][rel] += v; S[head][rel] += v
// ===========================================================================
__global__ void __launch_bounds__(256) fill_kernel(
    const int* __restrict__ heads,
    const int* __restrict__ tails,
    const int* __restrict__ rels,
    const float* __restrict__ val,
    int E)
{
    int stride = gridDim.x * blockDim.x;
    for (int f = blockIdx.x * blockDim.x + threadIdx.x; f < E; f += stride) {
        int    r = rels[f];
        __half v = __float2half(val[f]);
        atomicAdd(g_S + (size_t)tails[f] * KPAD + r, v);
        atomicAdd(g_S + (size_t)heads[f] * KPAD + r, v);
    }
}

// ===========================================================================
// GEMM: out = relu(S @ Bt^T).  CTA = 128M x 128N tile. 256 thr / 8 warps,
// warp tile 32M x 64N, m16n8k16 HMMA, 2-stage cp.async pipeline.
// ===========================================================================
__global__ void __launch_bounds__(256) gemm_kernel(
    float* __restrict__ out, int num_ent)
{
    extern __shared__ char smem[];
    const uint32_t sb = smem_u32(smem);

    const int tid  = threadIdx.x;
    const int lane = tid & 31;
    const int wid  = tid >> 5;
    const int m0   = blockIdx.x * 128;
    const int mo   = (wid >> 1) * 32;   // warp M offset within tile
    const int no   = (wid & 1) * 64;    // warp N offset within tile

    float acc[2][8][4];
#pragma unroll
    for (int i = 0; i < 2; i++)
#pragma unroll
        for (int j = 0; j < 8; j++)
#pragma unroll
            for (int k = 0; k < 4; k++) acc[i][j][k] = 0.f;

    // ---- stage loader: A rows = S[m0+row], B rows = Bt[row]; 128B rows ----
    auto load_stage = [&](int s, int buf) {
        const int k0 = s * KB;
        const uint32_t bA = sb + buf * STG_BYTES;
        const uint32_t bB = bA + 16384;
#pragma unroll
        for (int i = 0; i < 4; i++) {
            int idx = tid + i * 256;          // 0..1023
            int row = idx >> 3, c = idx & 7;
            cp_async16(bA + SWZ_OFF(row, c),
                       g_S + (size_t)(m0 + row) * KPAD + k0 + c * 8);
            cp_async16(bB + SWZ_OFF(row, c),
                       g_Bt + (size_t)row * KPAD + k0 + c * 8);
        }
        asm volatile("cp.async.commit_group;" ::: "memory");
    };

    load_stage(0, 0);

    for (int s = 0; s < NCH; s++) {
        if (s + 1 < NCH) load_stage(s + 1, (s + 1) & 1);
        if (s + 1 < NCH)
            asm volatile("cp.async.wait_group 1;" ::: "memory");
        else
            asm volatile("cp.async.wait_group 0;" ::: "memory");
        __syncthreads();

        const uint32_t bA = sb + (s & 1) * STG_BYTES;
        const uint32_t bB = bA + 16384;

#pragma unroll
        for (int ks = 0; ks < 4; ks++) {       // four k16 steps per chunk
            // A fragments: 2 x m16k16
            uint32_t a[2][4];
#pragma unroll
            for (int im = 0; im < 2; im++) {
                int row   = mo + im * 16 + (lane & 15);
                int chunk = ks * 2 + (lane >> 4);
                ldsm_x4(a[im][0], a[im][1], a[im][2], a[im][3],
                        bA + SWZ_OFF(row, chunk));
            }
            // B fragments: 4 x (n16 x k16) -> 8 n8 frags
            uint32_t br[4][4];
#pragma unroll
            for (int jn = 0; jn < 4; jn++) {
                int nrow  = no + jn * 16 + (lane & 7) + (((lane >> 3) & 1) << 3);
                int chunk = ks * 2 + (lane >> 4);
                ldsm_x4(br[jn][0], br[jn][1], br[jn][2], br[jn][3],
                        bB + SWZ_OFF(nrow, chunk));
            }
#pragma unroll
            for (int im = 0; im < 2; im++)
#pragma unroll
                for (int jn = 0; jn < 4; jn++) {
                    mma16816(acc[im][jn * 2 + 0], a[im], br[jn][0], br[jn][2]);
                    mma16816(acc[im][jn * 2 + 1], a[im], br[jn][1], br[jn][3]);
                }
        }
        __syncthreads();
    }

    // ---- epilogue: ReLU + store ----
#pragma unroll
    for (int im = 0; im < 2; im++) {
        int row0 = m0 + mo + im * 16 + (lane >> 2);
#pragma unroll
        for (int j = 0; j < 8; j++) {
            int col = no + j * 8 + (lane & 3) * 2;
            float* c = acc[im][j];
            if (row0 < num_ent) {
                float2 v = make_float2(fmaxf(c[0], 0.f), fmaxf(c[1], 0.f));
                *(float2*)(out + (size_t)row0 * HID + col) = v;
            }
            if (row0 + 8 < num_ent) {
                float2 v = make_float2(fmaxf(c[2], 0.f), fmaxf(c[3], 0.f));
                *(float2*)(out + (size_t)(row0 + 8) * HID + col) = v;
            }
        }
    }
}

// ===========================================================================
// Inputs: 0 local_entity(unused) 1 heads 2 tails 3 rels 4 val
//         5 rel_features[R,128] 6 W[128,128] 7 b[128]  -> out f32 [num_ent,128]
// ===========================================================================
extern "C" void kernel_launch(void* const* d_in, const int* in_sizes, int n_in,
                              void* d_out, int out_size)
{
    const int*   heads = (const int*)  d_in[1];
    const int*   tails = (const int*)  d_in[2];
    const int*   rels  = (const int*)  d_in[3];
    const float* val   = (const float*)d_in[4];
    const float* rel_f = (const float*)d_in[5];
    const float* W     = (const float*)d_in[6];
    const float* b     = (const float*)d_in[7];
    float*       out   = (float*)d_out;

    const int E       = in_sizes[1];
    const int R       = in_sizes[5] / HID;
    const int num_ent = out_size / HID;
    const int mtiles  = (num_ent + 127) / 128;

    void* sPtr = nullptr; void* bPtr = nullptr;
    cudaGetSymbolAddress(&sPtr, g_S);
    cudaGetSymbolAddress(&bPtr, g_Bt);
    cudaMemsetAsync(sPtr, 0, sizeof(__half) * (size_t)MAXE * KPAD);
    cudaMemsetAsync(bPtr, 0, sizeof(__half) * (size_t)HID * KPAD);

    const int TSM = (HID * 129 + HID) * sizeof(float);
    cudaFuncSetAttribute(transform_kernel,
                         cudaFuncAttributeMaxDynamicSharedMemorySize, TSM);
    cudaFuncSetAttribute(gemm_kernel,
                         cudaFuncAttributeMaxDynamicSharedMemorySize, SMEM_TOT);

    transform_kernel<<<148, HID, TSM>>>(rel_f, W, b, R);
    fill_kernel<<<2048, 256>>>(heads, tails, rels, val, E);
    gemm_kernel<<<mtiles, 256, SMEM_TOT>>>(out, num_ent);
}

// round 6
// speedup vs baseline: 2.6128x; 1.1248x over previous
#include <cuda_runtime.h>
#include <cuda_fp16.h>
#include <cstdint>

#define HID    128
#define KPAD   2048            // padded K (relations)
#define MAXE   16384           // padded entity rows
#define KB     64              // K per pipeline chunk (64 halves = 128 B rows)
#define NCH    (KPAD / KB)     // 32 chunks
#define STG_BYTES 32768        // A(16KB)+B(16KB) per stage
#define NSTAGES   3
#define SMEM_TOT  (NSTAGES * STG_BYTES)

// ---- static device scratch ----
__device__ __half g_S  [MAXE * KPAD];  // dense incidence-value matrix (64 MB)
__device__ __half g_Bt [HID  * KPAD];  // Bt[n][k]: transformed table, transposed (512 KB)
__device__ float  g_Wt [HID * HID];    // W transposed: Wt[i][o] = W[o][i]
__device__ float  g_T32[KPAD * HID];   // fp32 T[r][o] before transpose (1 MB)

// ===========================================================================
// helpers
// ===========================================================================
__device__ __forceinline__ uint32_t smem_u32(const void* p) {
    uint32_t a;
    asm("{ .reg .u64 t; cvta.to.shared.u64 t, %1; cvt.u32.u64 %0, t; }"
        : "=r"(a) : "l"(p));
    return a;
}
__device__ __forceinline__ void cp_async16(uint32_t dst, const void* src) {
    asm volatile("cp.async.cg.shared.global [%0], [%1], 16;"
                 :: "r"(dst), "l"(src) : "memory");
}
__device__ __forceinline__ void ldsm_x4(uint32_t& r0, uint32_t& r1,
                                        uint32_t& r2, uint32_t& r3, uint32_t a) {
    asm volatile("ldmatrix.sync.aligned.m8n8.x4.shared.b16 {%0,%1,%2,%3}, [%4];"
                 : "=r"(r0), "=r"(r1), "=r"(r2), "=r"(r3) : "r"(a));
}
__device__ __forceinline__ void mma16816(float* c, const uint32_t* a,
                                         uint32_t b0, uint32_t b1) {
    asm volatile(
        "mma.sync.aligned.m16n8k16.row.col.f32.f16.f16.f32 "
        "{%0,%1,%2,%3}, {%4,%5,%6,%7}, {%8,%9}, {%0,%1,%2,%3};"
        : "+f"(c[0]), "+f"(c[1]), "+f"(c[2]), "+f"(c[3])
        : "r"(a[0]), "r"(a[1]), "r"(a[2]), "r"(a[3]), "r"(b0), "r"(b1));
}
#define SWZ_OFF(row, chunk) (((row) * 128) + ((((chunk) ^ ((row) & 7))) << 4))

// ===========================================================================
// W transpose: Wt[i][o] = W[o][i]   (128x128 f32, 16 tiles of 32x32)
// ===========================================================================
__global__ void __launch_bounds__(256) wtrans_kernel(const float* __restrict__ W)
{
    __shared__ float t[32][33];
    const int tx = threadIdx.x & 31, ty = threadIdx.x >> 5;   // 32 x 8
    const int bi = (blockIdx.x & 3) * 32;   // i tile
    const int bo = (blockIdx.x >> 2) * 32;  // o tile
#pragma unroll
    for (int j = 0; j < 4; j++)
        t[ty + j * 8][tx] = W[(bo + ty + j * 8) * HID + bi + tx];
    __syncthreads();
#pragma unroll
    for (int j = 0; j < 4; j++)
        g_Wt[(bi + ty + j * 8) * HID + bo + tx] = t[tx][ty + j * 8];
}

// ===========================================================================
// Transform: T32[r][o] = b[o] + sum_i x[r][i] * Wt[i][o].  Warp per relation.
// ===========================================================================
__global__ void __launch_bounds__(256) transform_kernel(
    const float* __restrict__ rel_features,
    const float* __restrict__ b,
    int R)
{
    __shared__ float xs[8][HID];
    const int wid  = threadIdx.x >> 5;
    const int lane = threadIdx.x & 31;
    const int r    = blockIdx.x * 8 + wid;
    if (r >= R) return;

    ((float4*)xs[wid])[lane] = ((const float4*)(rel_features + (size_t)r * HID))[lane];
    __syncwarp();

    float4 acc = ((const float4*)b)[lane];
    const float4* __restrict__ Wt4 = (const float4*)g_Wt;
#pragma unroll 8
    for (int i = 0; i < HID; i++) {
        float  xi = xs[wid][i];
        float4 w  = Wt4[i * 32 + lane];
        acc.x = fmaf(xi, w.x, acc.x);
        acc.y = fmaf(xi, w.y, acc.y);
        acc.z = fmaf(xi, w.z, acc.z);
        acc.w = fmaf(xi, w.w, acc.w);
    }
    ((float4*)(g_T32 + (size_t)r * HID))[lane] = acc;
}

// ===========================================================================
// T transpose + f32->f16: Bt[o][r] = (half)T32[r][o]; zero-fills r >= R.
// grid: (KPAD/32) x (HID/32) tiles, block 256.
// ===========================================================================
__global__ void __launch_bounds__(256) ttrans_kernel(int R)
{
    __shared__ float t[32][33];
    const int tx = threadIdx.x & 31, ty = threadIdx.x >> 5;
    const int r0 = blockIdx.x * 32;
    const int o0 = blockIdx.y * 32;
#pragma unroll
    for (int j = 0; j < 4; j++) {
        int r = r0 + ty + j * 8;
        t[ty + j * 8][tx] = (r < R) ? g_T32[(size_t)r * HID + o0 + tx] : 0.f;
    }
    __syncthreads();
#pragma unroll
    for (int j = 0; j < 4; j++)
        g_Bt[(size_t)(o0 + ty + j * 8) * KPAD + r0 + tx] =
            __float2half(t[tx][ty + j * 8]);
}

// ===========================================================================
// Fill dense S with fp16 L2 atomics: S[tail][rel] += v; S[head][rel] += v
// ===========================================================================
__global__ void __launch_bounds__(256) fill_kernel(
    const int* __restrict__ heads,
    const int* __restrict__ tails,
    const int* __restrict__ rels,
    const float* __restrict__ val,
    int E)
{
    int stride = gridDim.x * blockDim.x;
    for (int f = blockIdx.x * blockDim.x + threadIdx.x; f < E; f += stride) {
        int    r = rels[f];
        __half v = __float2half(val[f]);
        atomicAdd(g_S + (size_t)tails[f] * KPAD + r, v);
        atomicAdd(g_S + (size_t)heads[f] * KPAD + r, v);
    }
}

// ===========================================================================
// GEMM: out = relu(S @ Bt^T).  CTA = 128M x 128N tile, 256 thr / 8 warps,
// warp tile 32M x 64N, m16n8k16 HMMA, 3-stage cp.async pipeline.
// ===========================================================================
__global__ void __launch_bounds__(256) gemm_kernel(
    float* __restrict__ out, int num_ent)
{
    extern __shared__ char smem[];
    const uint32_t sb = smem_u32(smem);

    const int tid  = threadIdx.x;
    const int lane = tid & 31;
    const int wid  = tid >> 5;
    const int m0   = blockIdx.x * 128;
    const int mo   = (wid >> 1) * 32;
    const int no   = (wid & 1) * 64;

    float acc[2][8][4];
#pragma unroll
    for (int i = 0; i < 2; i++)
#pragma unroll
        for (int j = 0; j < 8; j++)
#pragma unroll
            for (int k = 0; k < 4; k++) acc[i][j][k] = 0.f;

    auto load_stage = [&](int s, int buf) {
        const int k0 = s * KB;
        const uint32_t bA = sb + buf * STG_BYTES;
        const uint32_t bB = bA + 16384;
#pragma unroll
        for (int i = 0; i < 4; i++) {
            int idx = tid + i * 256;          // 0..1023
            int row = idx >> 3, c = idx & 7;
            cp_async16(bA + SWZ_OFF(row, c),
                       g_S + (size_t)(m0 + row) * KPAD + k0 + c * 8);
            cp_async16(bB + SWZ_OFF(row, c),
                       g_Bt + (size_t)row * KPAD + k0 + c * 8);
        }
        asm volatile("cp.async.commit_group;" ::: "memory");
    };

    load_stage(0, 0);
    load_stage(1, 1);

    for (int s = 0; s < NCH; s++) {
        if (s + 2 < NCH) {
            load_stage(s + 2, (s + 2) % NSTAGES);
            asm volatile("cp.async.wait_group 2;" ::: "memory");
        } else if (s + 1 < NCH) {
            asm volatile("cp.async.wait_group 1;" ::: "memory");
        } else {
            asm volatile("cp.async.wait_group 0;" ::: "memory");
        }
        __syncthreads();

        const uint32_t bA = sb + (s % NSTAGES) * STG_BYTES;
        const uint32_t bB = bA + 16384;

#pragma unroll
        for (int ks = 0; ks < 4; ks++) {
            uint32_t a[2][4];
#pragma unroll
            for (int im = 0; im < 2; im++) {
                int row   = mo + im * 16 + (lane & 15);
                int chunk = ks * 2 + (lane >> 4);
                ldsm_x4(a[im][0], a[im][1], a[im][2], a[im][3],
                        bA + SWZ_OFF(row, chunk));
            }
            uint32_t br[4][4];
#pragma unroll
            for (int jn = 0; jn < 4; jn++) {
                int nrow  = no + jn * 16 + (lane & 7) + (((lane >> 3) & 1) << 3);
                int chunk = ks * 2 + (lane >> 4);
                ldsm_x4(br[jn][0], br[jn][1], br[jn][2], br[jn][3],
                        bB + SWZ_OFF(nrow, chunk));
            }
#pragma unroll
            for (int im = 0; im < 2; im++)
#pragma unroll
                for (int jn = 0; jn < 4; jn++) {
                    mma16816(acc[im][jn * 2 + 0], a[im], br[jn][0], br[jn][2]);
                    mma16816(acc[im][jn * 2 + 1], a[im], br[jn][1], br[jn][3]);
                }
        }
        __syncthreads();
    }

    // epilogue: ReLU + store
#pragma unroll
    for (int im = 0; im < 2; im++) {
        int row0 = m0 + mo + im * 16 + (lane >> 2);
#pragma unroll
        for (int j = 0; j < 8; j++) {
            int col = no + j * 8 + (lane & 3) * 2;
            float* c = acc[im][j];
            if (row0 < num_ent) {
                float2 v = make_float2(fmaxf(c[0], 0.f), fmaxf(c[1], 0.f));
                *(float2*)(out + (size_t)row0 * HID + col) = v;
            }
            if (row0 + 8 < num_ent) {
                float2 v = make_float2(fmaxf(c[2], 0.f), fmaxf(c[3], 0.f));
                *(float2*)(out + (size_t)(row0 + 8) * HID + col) = v;
            }
        }
    }
}

// ===========================================================================
// Inputs: 0 local_entity(unused) 1 heads 2 tails 3 rels 4 val
//         5 rel_features[R,128] 6 W[128,128] 7 b[128]  -> out f32 [num_ent,128]
// ===========================================================================
extern "C" void kernel_launch(void* const* d_in, const int* in_sizes, int n_in,
                              void* d_out, int out_size)
{
    const int*   heads = (const int*)  d_in[1];
    const int*   tails = (const int*)  d_in[2];
    const int*   rels  = (const int*)  d_in[3];
    const float* val   = (const float*)d_in[4];
    const float* rel_f = (const float*)d_in[5];
    const float* W     = (const float*)d_in[6];
    const float* b     = (const float*)d_in[7];
    float*       out   = (float*)d_out;

    const int E       = in_sizes[1];
    const int R       = in_sizes[5] / HID;
    const int num_ent = out_size / HID;
    const int mtiles  = (num_ent + 127) / 128;

    void* sPtr = nullptr;
    cudaGetSymbolAddress(&sPtr, g_S);
    cudaMemsetAsync(sPtr, 0, sizeof(__half) * (size_t)MAXE * KPAD);

    cudaFuncSetAttribute(gemm_kernel,
                         cudaFuncAttributeMaxDynamicSharedMemorySize, SMEM_TOT);

    wtrans_kernel<<<16, 256>>>(W);
    transform_kernel<<<(R + 7) / 8, 256>>>(rel_f, b, R);
    {
        dim3 g(KPAD / 32, HID / 32);
        ttrans_kernel<<<g, 256>>>(R);
    }
    fill_kernel<<<2048, 256>>>(heads, tails, rels, val, E);
    gemm_kernel<<<mtiles, 256, SMEM_TOT>>>(out, num_ent);
}